// round 2
// baseline (speedup 1.0000x reference)
#include <cuda_runtime.h>

#define BB 16
#define CC 256
#define TT 2048
#define KK 2048
#define BT (BB*TT)            // 32768 rows
#define QOFF (BB*CC*TT)       // 8388608 quant elements

// ---------------- device scratch (no allocations allowed) ----------------
__device__ float  g_ecT[CC*KK];     // transposed codebook [c][n]  (2 MB)
__device__ float  g_esq[KK];        // ||e||^2 per codeword
__device__ float  g_xsq[BT];        // ||x_row||^2 per row
__device__ int    g_idx[BT];        // argmin index per row
__device__ double g_part[BB*(TT/32)]; // 1024 per-block loss partials

typedef unsigned long long u64;

// ---------------- packed f32x2 helpers (sm_103a) ----------------
__device__ __forceinline__ u64 pk2(float lo, float hi){
    u64 r; asm("mov.b64 %0, {%1,%2};" : "=l"(r) : "f"(lo), "f"(hi)); return r;
}
__device__ __forceinline__ u64 ffma2(u64 a, u64 b, u64 c){
    u64 d; asm("fma.rn.f32x2 %0, %1, %2, %3;" : "=l"(d) : "l"(a), "l"(b), "l"(c)); return d;
}
__device__ __forceinline__ u64 fadd2(u64 a, u64 b){
    u64 d; asm("add.rn.f32x2 %0, %1, %2;" : "=l"(d) : "l"(a), "l"(b)); return d;
}
__device__ __forceinline__ void up2(u64 v, float &lo, float &hi){
    asm("mov.b64 {%0,%1}, %2;" : "=f"(lo), "=f"(hi) : "l"(v));
}

// ---------------- prep kernels ----------------
__global__ void k_transpose(const float* __restrict__ cb){
    int i = blockIdx.x*256 + threadIdx.x;   // i = n*CC + c (c minor -> coalesced read)
    int n = i >> 8, c = i & 255;
    g_ecT[c*KK + n] = cb[i];
}

// e_sq: sequential sum of rounded squares (match reference rounding; no FMA contraction)
__global__ void k_esq(const float* __restrict__ cb){
    int n = blockIdx.x*256 + threadIdx.x;
    const float* row = cb + (size_t)n*CC;
    float acc = 0.f;
    for (int c = 0; c < CC; c++){
        float v = row[c];
        acc = __fadd_rn(acc, __fmul_rn(v, v));
    }
    g_esq[n] = acc;
}

// x_sq per row r=b*TT+t, sequential over channel c (stride-T loads, coalesced over t)
__global__ void k_xsq(const float* __restrict__ x){
    int r = blockIdx.x*256 + threadIdx.x;
    int b = r / TT, t = r % TT;
    const float* base = x + (size_t)b*CC*TT + t;
    float acc = 0.f;
    for (int c = 0; c < CC; c++){
        float v = base[(size_t)c*TT];
        acc = __fadd_rn(acc, __fmul_rn(v, v));
    }
    g_xsq[r] = acc;
}

// ---------------- main: fused distance-GEMM + running argmin ----------------
// Block: 128 rows (one batch b, contiguous t) x full N sweep in 128-wide tiles.
// 256 threads (16x16), per-thread 8x8 (4+4 split at offsets 0/64), f32x2 FMA.
__global__ void __launch_bounds__(256, 2)
k_main(const float* __restrict__ x, float* __restrict__ dout, int write_extras){
    __shared__ float xs[16][128];
    __shared__ float es[16][128];
    __shared__ float rv[128][17];
    __shared__ int   ri[128][17];

    const int tid = threadIdx.x;
    const int tx = tid & 15, ty = tid >> 4;
    const int m0 = blockIdx.x * 128;
    const int b  = m0 / TT, t0 = m0 % TT;
    const float* xb = x + (size_t)b*CC*TT;

    // per-thread row ||x||^2 (constant across N tiles)
    float xq[8];
    {
        float4 a = *(const float4*)&g_xsq[m0 + ty*4];
        float4 c = *(const float4*)&g_xsq[m0 + 64 + ty*4];
        xq[0]=a.x; xq[1]=a.y; xq[2]=a.z; xq[3]=a.w;
        xq[4]=c.x; xq[5]=c.y; xq[6]=c.z; xq[7]=c.w;
    }

    float bestv[8]; int besti[8];
    #pragma unroll
    for (int i = 0; i < 8; i++){ bestv[i] = 3.4e38f; besti[i] = 0; }

    const u64 NEG2 = pk2(-2.f, -2.f);

    for (int nt = 0; nt < KK/128; nt++){
        const int n0 = nt * 128;
        u64 acc[8][4];
        #pragma unroll
        for (int r = 0; r < 8; r++)
            #pragma unroll
            for (int p = 0; p < 4; p++) acc[r][p] = 0ull;

        for (int kc = 0; kc < 16; kc++){
            __syncthreads();
            {
                int f = tid;
                #pragma unroll
                for (int it = 0; it < 2; it++, f += 256){
                    int kk = f >> 5, tj = (f & 31) << 2;
                    *(float4*)&xs[kk][tj] =
                        *(const float4*)&xb[(size_t)(kc*16 + kk)*TT + t0 + tj];
                    *(float4*)&es[kk][tj] =
                        *(const float4*)&g_ecT[(size_t)(kc*16 + kk)*KK + n0 + tj];
                }
            }
            __syncthreads();
            #pragma unroll
            for (int k = 0; k < 16; k++){
                float4 a0 = *(float4*)&xs[k][ty*4];
                float4 a1 = *(float4*)&xs[k][64 + ty*4];
                float4 b0 = *(float4*)&es[k][tx*4];
                float4 b1 = *(float4*)&es[k][64 + tx*4];
                u64 bp[4] = { pk2(b0.x,b0.y), pk2(b0.z,b0.w),
                              pk2(b1.x,b1.y), pk2(b1.z,b1.w) };
                float av[8] = {a0.x,a0.y,a0.z,a0.w,a1.x,a1.y,a1.z,a1.w};
                #pragma unroll
                for (int r = 0; r < 8; r++){
                    u64 ad = pk2(av[r], av[r]);
                    #pragma unroll
                    for (int p = 0; p < 4; p++)
                        acc[r][p] = ffma2(bp[p], ad, acc[r][p]);
                }
            }
        }

        // epilogue: d2 = fl(fl(x_sq - 2m) + e_sq), running argmin (lowest-index ties)
        float4 eA = *(const float4*)&g_esq[n0 + tx*4];
        float4 eB = *(const float4*)&g_esq[n0 + 64 + tx*4];
        u64 ep[4] = { pk2(eA.x,eA.y), pk2(eA.z,eA.w), pk2(eB.x,eB.y), pk2(eB.z,eB.w) };
        #pragma unroll
        for (int r = 0; r < 8; r++){
            u64 xqp = pk2(xq[r], xq[r]);
            float d[8];
            #pragma unroll
            for (int p = 0; p < 4; p++){
                u64 t  = ffma2(acc[r][p], NEG2, xqp);  // round(x_sq - 2m)
                u64 dd = fadd2(t, ep[p]);              // + e_sq (second rounding)
                up2(dd, d[p*2], d[p*2+1]);
            }
            float tmin = fminf(fminf(fminf(d[0],d[1]), fminf(d[2],d[3])),
                               fminf(fminf(d[4],d[5]), fminf(d[6],d[7])));
            if (tmin < bestv[r]){
                bestv[r] = tmin;
                int c = 0;
                #pragma unroll
                for (int q = 7; q >= 0; q--){      // descending -> lowest col wins
                    int col = (q < 4) ? (n0 + tx*4 + q) : (n0 + 64 + tx*4 + (q-4));
                    if (d[q] == tmin) c = col;
                }
                besti[r] = c;
            }
        }
    }

    __syncthreads();
    #pragma unroll
    for (int i = 0; i < 8; i++){
        int row = (i < 4) ? (ty*4 + i) : (64 + ty*4 + (i-4));
        rv[row][tx] = bestv[i];
        ri[row][tx] = besti[i];
    }
    __syncthreads();
    if (tid < 128){
        float bv = rv[tid][0]; int bi = ri[tid][0];
        #pragma unroll
        for (int j = 1; j < 16; j++){
            float v = rv[tid][j]; int ii = ri[tid][j];
            if (v < bv || (v == bv && ii < bi)){ bv = v; bi = ii; }
        }
        g_idx[m0 + tid] = bi;
        if (write_extras) dout[QOFF + 2 + m0 + tid] = (float)bi;
    }
}

// ---------------- gather + transpose-store + MSE partials ----------------
__global__ void k_gather(const float* __restrict__ x, const float* __restrict__ cb,
                         float* __restrict__ dout){
    __shared__ float qs[32][257];
    __shared__ int   sidx[32];
    __shared__ double wsum[8];
    const int tid = threadIdx.x;
    const int bx = blockIdx.x;
    const int b = bx >> 6, t0 = (bx & 63) << 5;

    if (tid < 32) sidx[tid] = g_idx[b*TT + t0 + tid];
    __syncthreads();
    #pragma unroll 4
    for (int it = 0; it < 32; it++)
        qs[it][tid] = cb[(size_t)sidx[it]*CC + tid];   // coalesced row copy
    __syncthreads();

    float acc = 0.f;
    const int ttl = tid & 31, cbase = tid >> 5;
    for (int it = 0; it < 32; it++){
        int c = it*8 + cbase;
        float v = qs[ttl][c];                          // conflict-free (pad 257)
        size_t go = (size_t)(b*CC + c)*TT + t0 + ttl;  // coalesced 128B stores
        float xv = x[go];
        float dd = v - xv;
        acc += dd*dd;
        dout[go] = v;
    }
    #pragma unroll
    for (int o = 16; o > 0; o >>= 1) acc += __shfl_down_sync(0xffffffffu, acc, o);
    if ((tid & 31) == 0) wsum[tid >> 5] = (double)acc;
    __syncthreads();
    if (tid == 0){
        double s = 0;
        #pragma unroll
        for (int w = 0; w < 8; w++) s += wsum[w];
        g_part[bx] = s;
    }
}

__global__ void k_loss(float* __restrict__ dout, int write_extras){
    __shared__ double sm[256];
    const int tid = threadIdx.x;
    double s = 0;
    for (int j = tid; j < BB*(TT/32); j += 256) s += g_part[j];
    sm[tid] = s; __syncthreads();
    for (int o = 128; o > 0; o >>= 1){
        if (tid < o) sm[tid] += sm[tid + o];
        __syncthreads();
    }
    if (tid == 0 && write_extras){
        double mse = sm[0] / (double)QOFF;
        dout[QOFF]     = (float)mse;          // codebook_loss
        dout[QOFF + 1] = (float)(0.25*mse);   // commitment_loss (beta = 0.25)
    }
}

// ---------------- launch ----------------
extern "C" void kernel_launch(void* const* d_in, const int* in_sizes, int n_in,
                              void* d_out, int out_size){
    const float* x  = (const float*)d_in[0];
    const float* cb = (const float*)d_in[1];
    if (n_in >= 2 && in_sizes[0] == KK*CC && in_sizes[1] == BB*CC*TT){
        const float* t = x; x = cb; cb = t;   // defensive input-order swap
    }
    float* out = (float*)d_out;
    int write_extras = (out_size >= QOFF + 2 + BT) ? 1 : 0;

    k_transpose<<<(KK*CC)/256, 256>>>(cb);
    k_esq<<<KK/256, 256>>>(cb);
    k_xsq<<<BT/256, 256>>>(x);
    k_main<<<BT/128, 256>>>(x, out, write_extras);
    k_gather<<<BB*(TT/32), 256>>>(x, cb, out);
    k_loss<<<1, 256>>>(out, write_extras);
}

// round 5
// speedup vs baseline: 1.0362x; 1.0362x over previous
#include <cuda_runtime.h>

#define BB 16
#define CC 256
#define TT 2048
#define KK 2048
#define BT (BB*TT)            // 32768 rows
#define QOFF (BB*CC*TT)       // 8388608 quant elements

// ---------------- device scratch (no allocations allowed) ----------------
__device__ float  g_ecT[CC*KK];     // transposed codebook [c][n]  (2 MB)
__device__ float  g_esq[KK];        // ||e||^2 per codeword
__device__ float  g_xsq[BT];        // ||x_row||^2 per row
__device__ int    g_idx[BT];        // argmin index per row
__device__ double g_part[BB*(TT/32)]; // 1024 per-block loss partials

typedef unsigned long long u64;

// ---------------- packed f32x2 helpers (sm_103a) ----------------
__device__ __forceinline__ u64 pk2(float lo, float hi){
    u64 r; asm("mov.b64 %0, {%1,%2};" : "=l"(r) : "f"(lo), "f"(hi)); return r;
}
__device__ __forceinline__ u64 ffma2(u64 a, u64 b, u64 c){
    u64 d; asm("fma.rn.f32x2 %0, %1, %2, %3;" : "=l"(d) : "l"(a), "l"(b), "l"(c)); return d;
}
__device__ __forceinline__ u64 fadd2(u64 a, u64 b){
    u64 d; asm("add.rn.f32x2 %0, %1, %2;" : "=l"(d) : "l"(a), "l"(b)); return d;
}
__device__ __forceinline__ void up2(u64 v, float &lo, float &hi){
    asm("mov.b64 {%0,%1}, %2;" : "=f"(lo), "=f"(hi) : "l"(v));
}

// ---------------- cp.async helpers ----------------
__device__ __forceinline__ void cp16(void* smem_dst, const void* gmem_src){
    unsigned sa = (unsigned)__cvta_generic_to_shared(smem_dst);
    asm volatile("cp.async.cg.shared.global [%0], [%1], 16;" :: "r"(sa), "l"(gmem_src));
}
__device__ __forceinline__ void cp_commit(){
    asm volatile("cp.async.commit_group;" ::: "memory");
}
__device__ __forceinline__ void cp_wait0(){
    asm volatile("cp.async.wait_group 0;" ::: "memory");
}

// ---------------- prep kernels ----------------
__global__ void k_transpose(const float* __restrict__ cb){
    int i = blockIdx.x*256 + threadIdx.x;   // i = n*CC + c
    int n = i >> 8, c = i & 255;
    g_ecT[c*KK + n] = cb[i];
}

__global__ void k_esq(const float* __restrict__ cb){
    int n = blockIdx.x*256 + threadIdx.x;
    const float* row = cb + (size_t)n*CC;
    float acc = 0.f;
    for (int c = 0; c < CC; c++){
        float v = row[c];
        acc = __fadd_rn(acc, __fmul_rn(v, v));
    }
    g_esq[n] = acc;
}

__global__ void k_xsq(const float* __restrict__ x){
    int r = blockIdx.x*256 + threadIdx.x;
    int b = r / TT, t = r % TT;
    const float* base = x + (size_t)b*CC*TT + t;
    float acc = 0.f;
    for (int c = 0; c < CC; c++){
        float v = base[(size_t)c*TT];
        acc = __fadd_rn(acc, __fmul_rn(v, v));
    }
    g_xsq[r] = acc;
}

// ---------------- main: pipelined distance-GEMM + running argmin ----------------
// Block: 128 rows x 128-col N tiles, 256 threads (16x16), 8x8/thread via f32x2.
// 2-stage cp.async pipeline over 256 flat (nt,kc) stages of K-chunk 16.
#define NSTAGES 256

__global__ void __launch_bounds__(256, 2)
k_main(const float* __restrict__ x, float* __restrict__ dout, int write_extras){
    __shared__ float xs[2][16][128];   // 16 KB
    __shared__ float es[2][16][128];   // 16 KB

    const int tid = threadIdx.x;
    const int tx = tid & 15, ty = tid >> 4;
    const int m0 = blockIdx.x * 128;
    const int b  = m0 / TT, t0 = m0 % TT;
    const float* xb = x + (size_t)b*CC*TT;

    // per-thread row ||x||^2 (constant across N tiles)
    float xq[8];
    {
        float4 a = *(const float4*)&g_xsq[m0 + ty*4];
        float4 c = *(const float4*)&g_xsq[m0 + 64 + ty*4];
        xq[0]=a.x; xq[1]=a.y; xq[2]=a.z; xq[3]=a.w;
        xq[4]=c.x; xq[5]=c.y; xq[6]=c.z; xq[7]=c.w;
    }

    float bestv[8]; int besti[8];
    #pragma unroll
    for (int i = 0; i < 8; i++){ bestv[i] = 3.4e38f; besti[i] = 0; }

    const u64 NEG2 = pk2(-2.f, -2.f);

    // load-issue for flat stage s into buffer buf
    const int f0k = tid >> 5, f0j = (tid & 31) << 2;       // it=0: rows 0..7
    const int f1k = (tid + 256) >> 5, f1j = f0j;           // it=1: rows 8..15
    #define ISSUE(s, buf) do {                                              \
        int _nt = (s) >> 4, _kc = (s) & 15, _n0 = _nt << 7;                 \
        cp16(&xs[buf][f0k][f0j], &xb[(size_t)(_kc*16 + f0k)*TT + t0 + f0j]); \
        cp16(&es[buf][f0k][f0j], &g_ecT[(size_t)(_kc*16 + f0k)*KK + _n0 + f0j]); \
        cp16(&xs[buf][f1k][f1j], &xb[(size_t)(_kc*16 + f1k)*TT + t0 + f1j]); \
        cp16(&es[buf][f1k][f1j], &g_ecT[(size_t)(_kc*16 + f1k)*KK + _n0 + f1j]); \
        cp_commit();                                                        \
    } while(0)

    ISSUE(0, 0);

    u64 acc[8][4];

    for (int s = 0; s < NSTAGES; s++){
        const int nt = s >> 4, kc = s & 15, buf = s & 1;
        const int n0 = nt << 7;

        if (kc == 0){
            #pragma unroll
            for (int r = 0; r < 8; r++)
                #pragma unroll
                for (int p = 0; p < 4; p++) acc[r][p] = 0ull;
        }

        cp_wait0();            // stage s data landed
        __syncthreads();       // all warps done with buf^1 compute (prev stage)
        if (s + 1 < NSTAGES) ISSUE(s + 1, buf ^ 1);

        #pragma unroll
        for (int k = 0; k < 16; k++){
            float4 a0 = *(float4*)&xs[buf][k][ty*4];
            float4 a1 = *(float4*)&xs[buf][k][64 + ty*4];
            float4 b0 = *(float4*)&es[buf][k][tx*4];
            float4 b1 = *(float4*)&es[buf][k][64 + tx*4];
            u64 bp[4] = { pk2(b0.x,b0.y), pk2(b0.z,b0.w),
                          pk2(b1.x,b1.y), pk2(b1.z,b1.w) };
            float av[8] = {a0.x,a0.y,a0.z,a0.w,a1.x,a1.y,a1.z,a1.w};
            #pragma unroll
            for (int r = 0; r < 8; r++){
                u64 ad = pk2(av[r], av[r]);
                #pragma unroll
                for (int p = 0; p < 4; p++)
                    acc[r][p] = ffma2(bp[p], ad, acc[r][p]);
            }
        }

        if (kc == 15){
            // epilogue: d2 = fl(fl(x_sq - 2m) + e_sq), running argmin (lowest index ties)
            float4 eA = *(const float4*)&g_esq[n0 + tx*4];
            float4 eB = *(const float4*)&g_esq[n0 + 64 + tx*4];
            u64 ep[4] = { pk2(eA.x,eA.y), pk2(eA.z,eA.w), pk2(eB.x,eB.y), pk2(eB.z,eB.w) };
            #pragma unroll
            for (int r = 0; r < 8; r++){
                u64 xqp = pk2(xq[r], xq[r]);
                float d[8];
                #pragma unroll
                for (int p = 0; p < 4; p++){
                    u64 t  = ffma2(acc[r][p], NEG2, xqp);
                    u64 dd = fadd2(t, ep[p]);
                    up2(dd, d[p*2], d[p*2+1]);
                }
                float tmin = fminf(fminf(fminf(d[0],d[1]), fminf(d[2],d[3])),
                                   fminf(fminf(d[4],d[5]), fminf(d[6],d[7])));
                if (tmin < bestv[r]){
                    bestv[r] = tmin;
                    int c = 0;
                    #pragma unroll
                    for (int q = 7; q >= 0; q--){
                        int col = (q < 4) ? (n0 + tx*4 + q) : (n0 + 64 + tx*4 + (q-4));
                        if (d[q] == tmin) c = col;
                    }
                    besti[r] = c;
                }
            }
        }
    }

    // cross-thread argmin reduction; reuse pipeline smem (aliased) after sync
    __syncthreads();
    float* rv = &xs[0][0][0];               // 128*17 floats = 8704 B < 16 KB
    int*   ri = (int*)&es[0][0][0];
    #pragma unroll
    for (int i = 0; i < 8; i++){
        int row = (i < 4) ? (ty*4 + i) : (64 + ty*4 + (i-4));
        rv[row*17 + tx] = bestv[i];
        ri[row*17 + tx] = besti[i];
    }
    __syncthreads();
    if (tid < 128){
        float bv = rv[tid*17]; int bi = ri[tid*17];
        #pragma unroll
        for (int j = 1; j < 16; j++){
            float v = rv[tid*17 + j]; int ii = ri[tid*17 + j];
            if (v < bv || (v == bv && ii < bi)){ bv = v; bi = ii; }
        }
        g_idx[m0 + tid] = bi;
        if (write_extras) dout[QOFF + 2 + m0 + tid] = (float)bi;
    }
}

// ---------------- gather + transpose-store + MSE partials ----------------
__global__ void k_gather(const float* __restrict__ x, const float* __restrict__ cb,
                         float* __restrict__ dout){
    __shared__ float qs[32][257];
    __shared__ int   sidx[32];
    __shared__ double wsum[8];
    const int tid = threadIdx.x;
    const int bx = blockIdx.x;
    const int b = bx >> 6, t0 = (bx & 63) << 5;

    if (tid < 32) sidx[tid] = g_idx[b*TT + t0 + tid];
    __syncthreads();
    #pragma unroll 4
    for (int it = 0; it < 32; it++)
        qs[it][tid] = cb[(size_t)sidx[it]*CC + tid];
    __syncthreads();

    float acc = 0.f;
    const int ttl = tid & 31, cbase = tid >> 5;
    for (int it = 0; it < 32; it++){
        int c = it*8 + cbase;
        float v = qs[ttl][c];
        size_t go = (size_t)(b*CC + c)*TT + t0 + ttl;
        float xv = x[go];
        float dd = v - xv;
        acc += dd*dd;
        dout[go] = v;
    }
    #pragma unroll
    for (int o = 16; o > 0; o >>= 1) acc += __shfl_down_sync(0xffffffffu, acc, o);
    if ((tid & 31) == 0) wsum[tid >> 5] = (double)acc;
    __syncthreads();
    if (tid == 0){
        double s = 0;
        #pragma unroll
        for (int w = 0; w < 8; w++) s += wsum[w];
        g_part[bx] = s;
    }
}

__global__ void k_loss(float* __restrict__ dout, int write_extras){
    __shared__ double sm[256];
    const int tid = threadIdx.x;
    double s = 0;
    for (int j = tid; j < BB*(TT/32); j += 256) s += g_part[j];
    sm[tid] = s; __syncthreads();
    for (int o = 128; o > 0; o >>= 1){
        if (tid < o) sm[tid] += sm[tid + o];
        __syncthreads();
    }
    if (tid == 0 && write_extras){
        double mse = sm[0] / (double)QOFF;
        dout[QOFF]     = (float)mse;          // codebook_loss
        dout[QOFF + 1] = (float)(0.25*mse);   // commitment_loss
    }
}

// ---------------- launch ----------------
extern "C" void kernel_launch(void* const* d_in, const int* in_sizes, int n_in,
                              void* d_out, int out_size){
    const float* x  = (const float*)d_in[0];
    const float* cb = (const float*)d_in[1];
    if (n_in >= 2 && in_sizes[0] == KK*CC && in_sizes[1] == BB*CC*TT){
        const float* t = x; x = cb; cb = t;   // defensive input-order swap
    }
    float* out = (float*)d_out;
    int write_extras = (out_size >= QOFF + 2 + BT) ? 1 : 0;

    k_transpose<<<(KK*CC)/256, 256>>>(cb);
    k_esq<<<KK/256, 256>>>(cb);
    k_xsq<<<BT/256, 256>>>(x);
    k_main<<<BT/128, 256>>>(x, out, write_extras);
    k_gather<<<BB*(TT/32), 256>>>(x, cb, out);
    k_loss<<<1, 256>>>(out, write_extras);
}